// round 7
// baseline (speedup 1.0000x reference)
#include <cuda_runtime.h>
#include <cuda_bf16.h>
#include <cstdint>

#define NB 8
#define NN 2048
#define NF 512

// ---------------- device scratch (allocation-free rule) ----------------
__device__ float g_s[NB * NN];
__device__ __nv_bfloat16 g_Ah[(size_t)NB * NN * NN];   // A+I hi, 64 MB
__device__ __nv_bfloat16 g_Al[(size_t)NB * NN * NN];   // A+I lo
__device__ __nv_bfloat16 g_Xh[(size_t)NB * NN * NF];
__device__ __nv_bfloat16 g_Xl[(size_t)NB * NN * NF];
__device__ __nv_bfloat16 g_Wh[(size_t)NF * NF];        // W row-major [k][f]
__device__ __nv_bfloat16 g_Wl[(size_t)NF * NF];
__device__ __nv_bfloat16 g_yh[(size_t)NB * NN * NF];   // y row-major [node][f]
__device__ __nv_bfloat16 g_yl[(size_t)NB * NN * NF];

// ---------------- helpers ----------------
__device__ __forceinline__ uint32_t smem_u32(const void* p) {
    uint32_t a;
    asm("{ .reg .u64 t; cvta.to.shared.u64 t, %1; cvt.u32.u64 %0, t; }"
        : "=r"(a) : "l"(p));
    return a;
}
__device__ __forceinline__ uint32_t swzA(uint32_t off) { return off ^ ((off >> 3) & 0x70); }

#define CP16(dst, src) \
    asm volatile("cp.async.cg.shared.global [%0], [%1], 16;" :: "r"(dst), "l"(src))
#define CP_COMMIT() asm volatile("cp.async.commit_group;" ::: "memory")

#define LDSM4(r0, r1, r2, r3, addr) \
    asm volatile("ldmatrix.sync.aligned.m8n8.x4.shared.b16 {%0,%1,%2,%3}, [%4];" \
                 : "=r"(r0), "=r"(r1), "=r"(r2), "=r"(r3) : "r"(addr))
#define LDSM4T(r0, r1, r2, r3, addr) \
    asm volatile("ldmatrix.sync.aligned.m8n8.x4.trans.shared.b16 {%0,%1,%2,%3}, [%4];" \
                 : "=r"(r0), "=r"(r1), "=r"(r2), "=r"(r3) : "r"(addr))

// NOT volatile: register constraints fully describe the op.
#define MMA16816(c, a, b) \
    asm("mma.sync.aligned.m16n8k16.row.col.f32.bf16.bf16.f32 " \
        "{%0,%1,%2,%3}, {%4,%5,%6,%7}, {%8,%9}, {%0,%1,%2,%3};" \
        : "+f"((c)[0]), "+f"((c)[1]), "+f"((c)[2]), "+f"((c)[3]) \
        : "r"((a)[0]), "r"((a)[1]), "r"((a)[2]), "r"((a)[3]), \
          "r"((b)[0]), "r"((b)[1]))

// ---------------- conversion kernels ----------------
__global__ void convA_kernel(const float* __restrict__ A) {
    const int row = blockIdx.x;                    // 0 .. NB*NN-1
    const int node = row & (NN - 1);
    const float* src = A + (size_t)row * NN;
    __nv_bfloat16* dh = g_Ah + (size_t)row * NN;
    __nv_bfloat16* dl = g_Al + (size_t)row * NN;
    const int t = threadIdx.x;                     // 256 thr, 8 elems each
    float4 v0 = *(const float4*)(src + t * 8);
    float4 v1 = *(const float4*)(src + t * 8 + 4);
    float v[8] = {v0.x, v0.y, v0.z, v0.w, v1.x, v1.y, v1.z, v1.w};
    if (node >= t * 8 && node < t * 8 + 8) v[node - t * 8] += 1.0f;   // +I
    alignas(16) __nv_bfloat16 h[8];
    alignas(16) __nv_bfloat16 l[8];
    float sum = 0.f;
    #pragma unroll
    for (int i = 0; i < 8; i++) {
        sum += v[i];
        h[i] = __float2bfloat16(v[i]);
        l[i] = __float2bfloat16(v[i] - __bfloat162float(h[i]));
    }
    *(uint4*)(dh + t * 8) = *(uint4*)h;
    *(uint4*)(dl + t * 8) = *(uint4*)l;
    __shared__ float red[8];
    #pragma unroll
    for (int o = 16; o; o >>= 1) sum += __shfl_down_sync(0xffffffff, sum, o);
    if ((t & 31) == 0) red[t >> 5] = sum;
    __syncthreads();
    if (t == 0) {
        float tot = 0.0f;
        #pragma unroll
        for (int w = 0; w < 8; w++) tot += red[w];
        g_s[row] = rsqrtf(tot);
    }
}

__global__ void conv_hl_kernel(const float* __restrict__ src_,
                               __nv_bfloat16* __restrict__ dh_,
                               __nv_bfloat16* __restrict__ dl_) {
    const int row = blockIdx.x;
    const float* src = src_ + (size_t)row * NF;
    __nv_bfloat16* dh = dh_ + (size_t)row * NF;
    __nv_bfloat16* dl = dl_ + (size_t)row * NF;
    const int t = threadIdx.x;                     // 64 thr, 8 elems each
    float4 v0 = *(const float4*)(src + t * 8);
    float4 v1 = *(const float4*)(src + t * 8 + 4);
    float v[8] = {v0.x, v0.y, v0.z, v0.w, v1.x, v1.y, v1.z, v1.w};
    alignas(16) __nv_bfloat16 h[8];
    alignas(16) __nv_bfloat16 l[8];
    #pragma unroll
    for (int i = 0; i < 8; i++) {
        h[i] = __float2bfloat16(v[i]);
        l[i] = __float2bfloat16(v[i] - __bfloat162float(h[i]));
    }
    *(uint4*)(dh + t * 8) = *(uint4*)h;
    *(uint4*)(dl + t * 8) = *(uint4*)l;
}

// ---------------- HMMA GEMM ----------------
// CTA tile M=128, N=256, Kchunk=64. 512 threads, 16 warps = 4(m) x 4(n);
// warp tile 32x64 -> 4 warps per SMSP for HMMA latency hiding.
// A [m][k] K-major pitch 128B (SW128). B [k][n] row-major pitch 512B with XOR
// swizzle, trans-LDSM. 3-term split D = AhBh + AhBl + AlBh.
#define OFF_AH 0
#define OFF_AL 16384
#define OFF_BH 32768
#define OFF_BL 65536
#define STAGE_BYTES 98304
#define SMEM_TOTAL (2 * STAGE_BYTES)
#define NTHR 512

template <int KTOT, bool IS_XW>
__global__ __launch_bounds__(NTHR, 1)
void gemm_kernel(const float* __restrict__ bias, float* __restrict__ out) {
    constexpr int NCH = KTOT / 64;
    extern __shared__ __align__(1024) char smem[];
    const uint32_t sb = smem_u32(smem);

    const int tid = threadIdx.x;
    const int wid = tid >> 5;
    const int lane = tid & 31;
    const int wm = wid >> 2;       // 4 m-tiles of 32
    const int wn = wid & 3;        // 4 n-tiles of 64

    const int bb = blockIdx.z;
    const int m0 = blockIdx.y * 128;
    const int n0 = blockIdx.x * 256;

    const __nv_bfloat16 *pAh, *pAl, *pBh, *pBl;
    size_t lda;
    if (IS_XW) {
        lda = NF;
        pAh = g_Xh + ((size_t)bb * NN + m0) * NF;
        pAl = g_Xl + ((size_t)bb * NN + m0) * NF;
        pBh = g_Wh + n0;
        pBl = g_Wl + n0;
    } else {
        lda = NN;
        pAh = g_Ah + ((size_t)bb * NN + m0) * NN;
        pAl = g_Al + ((size_t)bb * NN + m0) * NN;
        pBh = g_yh + (size_t)bb * NN * NF + n0;
        pBl = g_yl + (size_t)bb * NN * NF + n0;
    }

    auto load_stage = [&](int s, int chunk) {
        const uint32_t base = sb + (uint32_t)s * STAGE_BYTES;
        const int k0 = chunk * 64;
        #pragma unroll
        for (int i = 0; i < 2; i++) {              // A: 128 rows x 8 x 16B (h+l)
            int g = tid + i * NTHR;
            int r = g >> 3, c = g & 7;
            uint32_t so = swzA((uint32_t)(r * 128 + c * 16));
            CP16(base + OFF_AH + so, (const char*)(pAh + (size_t)r * lda + k0) + c * 16);
            CP16(base + OFF_AL + so, (const char*)(pAl + (size_t)r * lda + k0) + c * 16);
        }
        #pragma unroll
        for (int i = 0; i < 4; i++) {              // B: 64 k-rows x 32 x 16B (h+l)
            int g = tid + i * NTHR;
            int k = g >> 5, c = g & 31;
            uint32_t so = (uint32_t)(k * 512 + ((c * 16) ^ ((k & 7) << 4)));
            CP16(base + OFF_BH + so, (const char*)(pBh + (size_t)(k0 + k) * NF) + c * 16);
            CP16(base + OFF_BL + so, (const char*)(pBl + (size_t)(k0 + k) * NF) + c * 16);
        }
        CP_COMMIT();
    };

    float c[2][8][4];
    #pragma unroll
    for (int i = 0; i < 2; i++)
        #pragma unroll
        for (int j = 0; j < 8; j++)
            #pragma unroll
            for (int k = 0; k < 4; k++) c[i][j][k] = 0.f;

    const int a_row = wm * 32 + (lane & 15);
    const int a_kb  = (lane >> 4) * 16;
    const int b_krow = lane & 15;
    const uint32_t b_swz = (uint32_t)(b_krow & 7) << 4;
    const int b_nbyte = wn * 128 + (lane >> 4) * 16;

    load_stage(0, 0);

    #pragma unroll 1
    for (int i = 0; i < NCH; i++) {
        asm volatile("cp.async.wait_group 0;" ::: "memory");
        __syncthreads();
        if (i + 1 < NCH) load_stage((i + 1) & 1, i + 1);

        const uint32_t base = sb + (uint32_t)(i & 1) * STAGE_BYTES;
        #pragma unroll
        for (int ks = 0; ks < 4; ks++) {
            uint32_t ah[2][4], al[2][4];
            #pragma unroll
            for (int mf = 0; mf < 2; mf++) {
                uint32_t off = swzA((uint32_t)((a_row + mf * 16) * 128 + ks * 32 + a_kb));
                LDSM4(ah[mf][0], ah[mf][1], ah[mf][2], ah[mf][3], base + OFF_AH + off);
                LDSM4(al[mf][0], al[mf][1], al[mf][2], al[mf][3], base + OFF_AL + off);
            }
            #pragma unroll
            for (int nb = 0; nb < 4; nb++) {
                uint32_t bh[2][2], bl[2][2];
                uint32_t addr = base + (uint32_t)((ks * 16 + b_krow) * 512) +
                                ((uint32_t)(b_nbyte + nb * 32) ^ b_swz);
                LDSM4T(bh[0][0], bh[0][1], bh[1][0], bh[1][1], addr + OFF_BH);
                LDSM4T(bl[0][0], bl[0][1], bl[1][0], bl[1][1], addr + OFF_BL);
                #pragma unroll
                for (int mf = 0; mf < 2; mf++) {
                    MMA16816(c[mf][2*nb],   ah[mf], bh[0]);
                    MMA16816(c[mf][2*nb+1], ah[mf], bh[1]);
                    MMA16816(c[mf][2*nb],   ah[mf], bl[0]);
                    MMA16816(c[mf][2*nb+1], ah[mf], bl[1]);
                    MMA16816(c[mf][2*nb],   al[mf], bh[0]);
                    MMA16816(c[mf][2*nb+1], al[mf], bh[1]);
                }
            }
        }
    }

    // ---------------- epilogue ----------------
    const int g4 = lane >> 2;
    const int tq = lane & 3;
    #pragma unroll
    for (int mf = 0; mf < 2; mf++) {
        #pragma unroll
        for (int half = 0; half < 2; half++) {
            const int m = m0 + wm * 32 + mf * 16 + g4 + half * 8;
            const float s = g_s[bb * NN + m];
            if (IS_XW) {
                __nv_bfloat16* yh = g_yh + ((size_t)bb * NN + m) * NF;
                __nv_bfloat16* yl = g_yl + ((size_t)bb * NN + m) * NF;
                #pragma unroll
                for (int nf = 0; nf < 8; nf++) {
                    const int f = n0 + wn * 64 + nf * 8 + tq * 2;
                    float2 bs = *(const float2*)(bias + f);
                    float y0 = s * (c[mf][nf][half * 2 + 0] + bs.x);
                    float y1 = s * (c[mf][nf][half * 2 + 1] + bs.y);
                    __nv_bfloat16 h0 = __float2bfloat16(y0);
                    __nv_bfloat16 h1 = __float2bfloat16(y1);
                    __nv_bfloat162 hv; hv.x = h0; hv.y = h1;
                    __nv_bfloat162 lv;
                    lv.x = __float2bfloat16(y0 - __bfloat162float(h0));
                    lv.y = __float2bfloat16(y1 - __bfloat162float(h1));
                    *(__nv_bfloat162*)(yh + f) = hv;
                    *(__nv_bfloat162*)(yl + f) = lv;
                }
            } else {
                float* orow = out + ((size_t)bb * NN + m) * NF;
                #pragma unroll
                for (int nf = 0; nf < 8; nf++) {
                    const int f = n0 + wn * 64 + nf * 8 + tq * 2;
                    float2 o;
                    o.x = s * c[mf][nf][half * 2 + 0];
                    o.y = s * c[mf][nf][half * 2 + 1];
                    *(float2*)(orow + f) = o;
                }
            }
        }
    }
}

// ---------------- launch ----------------
extern "C" void kernel_launch(void* const* d_in, const int* in_sizes, int n_in,
                              void* d_out, int out_size) {
    const float* X    = (const float*)d_in[0];   // [8,2048,512]
    const float* A    = (const float*)d_in[1];   // [8,2048,2048]
    const float* W    = (const float*)d_in[2];   // [512,512]
    const float* bias = (const float*)d_in[3];   // [512]
    float* out = (float*)d_out;                  // [8,2048,512]

    cudaFuncSetAttribute(gemm_kernel<NF, true>,
                         cudaFuncAttributeMaxDynamicSharedMemorySize, SMEM_TOTAL);
    cudaFuncSetAttribute(gemm_kernel<NN, false>,
                         cudaFuncAttributeMaxDynamicSharedMemorySize, SMEM_TOTAL);

    __nv_bfloat16 *dXh, *dXl, *dWh, *dWl;
    cudaGetSymbolAddress((void**)&dXh, g_Xh);
    cudaGetSymbolAddress((void**)&dXl, g_Xl);
    cudaGetSymbolAddress((void**)&dWh, g_Wh);
    cudaGetSymbolAddress((void**)&dWl, g_Wl);

    convA_kernel<<<NB * NN, 256>>>(A);                     // A+I -> hi/lo + degree
    conv_hl_kernel<<<NB * NN, 64>>>(X, dXh, dXl);          // X -> hi/lo
    conv_hl_kernel<<<NF, 64>>>(W, dWh, dWl);               // W -> hi/lo

    dim3 grid(NF / 256, NN / 128, NB);                     // (2, 16, 8) = 256 CTAs
    gemm_kernel<NF, true><<<grid, NTHR, SMEM_TOTAL>>>(bias, out);   // y = s*(XW+b)
    gemm_kernel<NN, false><<<grid, NTHR, SMEM_TOTAL>>>(bias, out);  // out = s*(Ahat@y)
}

// round 8
// speedup vs baseline: 2.1856x; 2.1856x over previous
#include <cuda_runtime.h>
#include <cuda_fp16.h>
#include <cstdint>

#define NB 8
#define NN 2048
#define NF 512

// ---------------- device scratch (allocation-free rule) ----------------
__device__ float g_s[NB * NN];
__device__ __half g_A[(size_t)NB * NN * NN];   // A+I fp16, 64 MB
__device__ __half g_X[(size_t)NB * NN * NF];   // 16 MB
__device__ __half g_W[(size_t)NF * NF];        // W row-major [k][f]
__device__ __half g_y[(size_t)NB * NN * NF];   // y row-major [node][f]

// ---------------- helpers ----------------
__device__ __forceinline__ uint32_t smem_u32(const void* p) {
    uint32_t a;
    asm("{ .reg .u64 t; cvta.to.shared.u64 t, %1; cvt.u32.u64 %0, t; }"
        : "=r"(a) : "l"(p));
    return a;
}
__device__ __forceinline__ uint32_t swzA(uint32_t off) { return off ^ ((off >> 3) & 0x70); }

#define CP16(dst, src) \
    asm volatile("cp.async.cg.shared.global [%0], [%1], 16;" :: "r"(dst), "l"(src))
#define CP_COMMIT() asm volatile("cp.async.commit_group;" ::: "memory")

#define LDSM4(r0, r1, r2, r3, addr) \
    asm volatile("ldmatrix.sync.aligned.m8n8.x4.shared.b16 {%0,%1,%2,%3}, [%4];" \
                 : "=r"(r0), "=r"(r1), "=r"(r2), "=r"(r3) : "r"(addr))
#define LDSM4T(r0, r1, r2, r3, addr) \
    asm volatile("ldmatrix.sync.aligned.m8n8.x4.trans.shared.b16 {%0,%1,%2,%3}, [%4];" \
                 : "=r"(r0), "=r"(r1), "=r"(r2), "=r"(r3) : "r"(addr))

#define MMA16816(c, a, b) \
    asm("mma.sync.aligned.m16n8k16.row.col.f32.f16.f16.f32 " \
        "{%0,%1,%2,%3}, {%4,%5,%6,%7}, {%8,%9}, {%0,%1,%2,%3};" \
        : "+f"((c)[0]), "+f"((c)[1]), "+f"((c)[2]), "+f"((c)[3]) \
        : "r"((a)[0]), "r"((a)[1]), "r"((a)[2]), "r"((a)[3]), \
          "r"((b)[0]), "r"((b)[1]))

// ---------------- conversion kernels ----------------
// A -> (A+I) fp16, fused degree: s = rsqrt(rowsum(A)+1)
__global__ void convA_kernel(const float* __restrict__ A) {
    const int row = blockIdx.x;                    // 0 .. NB*NN-1
    const int node = row & (NN - 1);
    const float* src = A + (size_t)row * NN;
    __half* d = g_A + (size_t)row * NN;
    const int t = threadIdx.x;                     // 256 thr, 8 elems each
    float4 v0 = *(const float4*)(src + t * 8);
    float4 v1 = *(const float4*)(src + t * 8 + 4);
    float v[8] = {v0.x, v0.y, v0.z, v0.w, v1.x, v1.y, v1.z, v1.w};
    if (node >= t * 8 && node < t * 8 + 8) v[node - t * 8] += 1.0f;   // +I
    alignas(16) __half h[8];
    float sum = 0.f;
    #pragma unroll
    for (int i = 0; i < 8; i++) {
        sum += v[i];
        h[i] = __float2half(v[i]);
    }
    *(uint4*)(d + t * 8) = *(uint4*)h;
    __shared__ float red[8];
    #pragma unroll
    for (int o = 16; o; o >>= 1) sum += __shfl_down_sync(0xffffffff, sum, o);
    if ((t & 31) == 0) red[t >> 5] = sum;
    __syncthreads();
    if (t == 0) {
        float tot = 0.0f;
        #pragma unroll
        for (int w = 0; w < 8; w++) tot += red[w];
        g_s[row] = rsqrtf(tot);
    }
}

__global__ void conv_kernel(const float* __restrict__ src_,
                            __half* __restrict__ dst_) {
    const int row = blockIdx.x;
    const float* src = src_ + (size_t)row * NF;
    __half* d = dst_ + (size_t)row * NF;
    const int t = threadIdx.x;                     // 64 thr, 8 elems each
    float4 v0 = *(const float4*)(src + t * 8);
    float4 v1 = *(const float4*)(src + t * 8 + 4);
    float v[8] = {v0.x, v0.y, v0.z, v0.w, v1.x, v1.y, v1.z, v1.w};
    alignas(16) __half h[8];
    #pragma unroll
    for (int i = 0; i < 8; i++) h[i] = __float2half(v[i]);
    *(uint4*)(d + t * 8) = *(uint4*)h;
}

// ---------------- HMMA GEMM (single fp16, 1 term) ----------------
// CTA tile M=128, N=256, Kchunk=64. 8 warps = 2(m) x 4(n); warp tile 64x64.
// A [m][k] K-major pitch 128B (SW128). B [k][n] row-major pitch 512B with XOR
// swizzle, trans-LDSM.
#define OFF_A 0
#define OFF_B 16384
#define STAGE_BYTES 49152
#define SMEM_TOTAL (2 * STAGE_BYTES)

template <int KTOT, bool IS_XW>
__global__ __launch_bounds__(256, 1)
void gemm_kernel(const float* __restrict__ bias, float* __restrict__ out) {
    constexpr int NCH = KTOT / 64;
    extern __shared__ __align__(1024) char smem[];
    const uint32_t sb = smem_u32(smem);

    const int tid = threadIdx.x;
    const int wid = tid >> 5;
    const int lane = tid & 31;
    const int wm = wid >> 2;       // 2 m-tiles of 64
    const int wn = wid & 3;        // 4 n-tiles of 64

    const int bb = blockIdx.z;
    const int m0 = blockIdx.y * 128;
    const int n0 = blockIdx.x * 256;

    const __half *pA, *pB;
    size_t lda;
    if (IS_XW) {
        lda = NF;
        pA = g_X + ((size_t)bb * NN + m0) * NF;
        pB = g_W + n0;                          // [k][n], ld = NF
    } else {
        lda = NN;
        pA = g_A + ((size_t)bb * NN + m0) * NN;
        pB = g_y + (size_t)bb * NN * NF + n0;   // y [node][f], ld = NF
    }

    auto load_stage = [&](int s, int chunk) {
        const uint32_t base = sb + (uint32_t)s * STAGE_BYTES;
        const int k0 = chunk * 64;
        #pragma unroll
        for (int i = 0; i < 4; i++) {              // A: 128 rows x 8 x 16B
            int g = tid + i * 256;
            int r = g >> 3, c = g & 7;
            uint32_t so = swzA((uint32_t)(r * 128 + c * 16));
            CP16(base + OFF_A + so, (const char*)(pA + (size_t)r * lda + k0) + c * 16);
        }
        #pragma unroll
        for (int i = 0; i < 8; i++) {              // B: 64 k-rows x 32 x 16B
            int g = tid + i * 256;
            int k = g >> 5, c = g & 31;
            uint32_t so = (uint32_t)(k * 512 + ((c * 16) ^ ((k & 7) << 4)));
            CP16(base + OFF_B + so, (const char*)(pB + (size_t)(k0 + k) * NF) + c * 16);
        }
        CP_COMMIT();
    };

    float c[4][8][4];
    #pragma unroll
    for (int i = 0; i < 4; i++)
        #pragma unroll
        for (int j = 0; j < 8; j++)
            #pragma unroll
            for (int k = 0; k < 4; k++) c[i][j][k] = 0.f;

    const int a_row = wm * 64 + (lane & 15);
    const int a_kb  = (lane >> 4) * 16;
    const int b_krow = lane & 15;
    const uint32_t b_swz = (uint32_t)(b_krow & 7) << 4;
    const int b_nbyte = wn * 128 + (lane >> 4) * 16;

    load_stage(0, 0);

    #pragma unroll 1
    for (int i = 0; i < NCH; i++) {
        asm volatile("cp.async.wait_group 0;" ::: "memory");
        __syncthreads();
        if (i + 1 < NCH) load_stage((i + 1) & 1, i + 1);

        const uint32_t base = sb + (uint32_t)(i & 1) * STAGE_BYTES;
        #pragma unroll
        for (int ks = 0; ks < 4; ks++) {
            uint32_t ah[4][4];
            #pragma unroll
            for (int mf = 0; mf < 4; mf++) {
                uint32_t off = swzA((uint32_t)((a_row + mf * 16) * 128 + ks * 32 + a_kb));
                LDSM4(ah[mf][0], ah[mf][1], ah[mf][2], ah[mf][3], base + OFF_A + off);
            }
            #pragma unroll
            for (int nb = 0; nb < 4; nb++) {
                uint32_t bh[2][2];
                uint32_t addr = base + (uint32_t)((ks * 16 + b_krow) * 512) +
                                ((uint32_t)(b_nbyte + nb * 32) ^ b_swz);
                LDSM4T(bh[0][0], bh[0][1], bh[1][0], bh[1][1], addr + OFF_B);
                #pragma unroll
                for (int mf = 0; mf < 4; mf++) MMA16816(c[mf][2*nb],   ah[mf], bh[0]);
                #pragma unroll
                for (int mf = 0; mf < 4; mf++) MMA16816(c[mf][2*nb+1], ah[mf], bh[1]);
            }
        }
    }

    // ---------------- epilogue ----------------
    const int g4 = lane >> 2;
    const int tq = lane & 3;
    #pragma unroll
    for (int mf = 0; mf < 4; mf++) {
        #pragma unroll
        for (int half = 0; half < 2; half++) {
            const int m = m0 + wm * 64 + mf * 16 + g4 + half * 8;
            const float s = g_s[bb * NN + m];
            if (IS_XW) {
                __half* yr = g_y + ((size_t)bb * NN + m) * NF;
                #pragma unroll
                for (int nf = 0; nf < 8; nf++) {
                    const int f = n0 + wn * 64 + nf * 8 + tq * 2;
                    float2 bs = *(const float2*)(bias + f);
                    __half2 hv;
                    hv.x = __float2half(s * (c[mf][nf][half * 2 + 0] + bs.x));
                    hv.y = __float2half(s * (c[mf][nf][half * 2 + 1] + bs.y));
                    *(__half2*)(yr + f) = hv;
                }
            } else {
                float* orow = out + ((size_t)bb * NN + m) * NF;
                #pragma unroll
                for (int nf = 0; nf < 8; nf++) {
                    const int f = n0 + wn * 64 + nf * 8 + tq * 2;
                    float2 o;
                    o.x = s * c[mf][nf][half * 2 + 0];
                    o.y = s * c[mf][nf][half * 2 + 1];
                    *(float2*)(orow + f) = o;
                }
            }
        }
    }
}

// ---------------- launch ----------------
extern "C" void kernel_launch(void* const* d_in, const int* in_sizes, int n_in,
                              void* d_out, int out_size) {
    const float* X    = (const float*)d_in[0];   // [8,2048,512]
    const float* A    = (const float*)d_in[1];   // [8,2048,2048]
    const float* W    = (const float*)d_in[2];   // [512,512]
    const float* bias = (const float*)d_in[3];   // [512]
    float* out = (float*)d_out;                  // [8,2048,512]

    cudaFuncSetAttribute(gemm_kernel<NF, true>,
                         cudaFuncAttributeMaxDynamicSharedMemorySize, SMEM_TOTAL);
    cudaFuncSetAttribute(gemm_kernel<NN, false>,
                         cudaFuncAttributeMaxDynamicSharedMemorySize, SMEM_TOTAL);

    __half *dX, *dW;
    cudaGetSymbolAddress((void**)&dX, g_X);
    cudaGetSymbolAddress((void**)&dW, g_W);

    convA_kernel<<<NB * NN, 256>>>(A);                     // A+I -> fp16 + degree
    conv_kernel<<<NB * NN, 64>>>(X, dX);                   // X -> fp16
    conv_kernel<<<NF, 64>>>(W, dW);                        // W -> fp16

    dim3 grid(NF / 256, NN / 128, NB);                     // (2, 16, 8) = 256 CTAs
    gemm_kernel<NF, true><<<grid, 256, SMEM_TOTAL>>>(bias, out);   // y = s*(XW+b)
    gemm_kernel<NN, false><<<grid, 256, SMEM_TOTAL>>>(bias, out);  // out = s*(Ahat@y)
}